// round 1
// baseline (speedup 1.0000x reference)
#include <cuda_runtime.h>

#define NBATCH   128
#define N_ATOMS  4096
#define NB       4095
#define NA       4094
#define NT       4093
#define MAX_LEN  (5 * NT)   /* 20465 */
#define ROW      9
#define EPS      1e-8f

#define NTHREADS 1024

// shared layout sizes (floats)
#define SM_COORDS (3 * N_ATOMS)   /* 12288 */
#define SM_BT     30
#define SM_AT     26
#define SM_TT     50
#define SM_MU     25
#define SM_RED    (3 * 32)
#define SMEM_FLOATS (SM_COORDS + SM_BT + SM_AT + SM_TT + SM_MU + SM_RED)
#define SMEM_BYTES  (SMEM_FLOATS * 4)

__global__ __launch_bounds__(NTHREADS, 1)
void local_energy_kernel(const float* __restrict__ feats,
                         const float* __restrict__ bond_type,
                         const float* __restrict__ angle_type,
                         const float* __restrict__ tor_type,
                         const int*   __restrict__ multiplicity,
                         const float* __restrict__ opt_pars,
                         float* __restrict__ out)
{
    extern __shared__ float smem[];
    float* sc   = smem;                 // coords, 3*N_ATOMS
    float* sbt  = sc  + SM_COORDS;      // bond_type [15][2]
    float* sat  = sbt + SM_BT;          // angle_type [13][2]
    float* stt  = sat + SM_AT;          // tor_type [25][2]
    float* smu  = stt + SM_TT;          // multiplicity as float [25]
    float* sred = smu + SM_MU;          // reduction scratch 3*32

    const int b   = blockIdx.x;
    const int tid = threadIdx.x;
    const float* f = feats + (size_t)b * MAX_LEN * ROW;

    // Stage coords column (col 5 of rows [0, 3*N_ATOMS)) into shared.
    #pragma unroll 4
    for (int i = tid; i < SM_COORDS; i += NTHREADS)
        sc[i] = __ldg(&f[(size_t)i * ROW + 5]);

    if (tid < SM_BT) sbt[tid] = bond_type[tid];
    else if (tid < SM_BT + SM_AT) sat[tid - SM_BT] = angle_type[tid - SM_BT];
    else if (tid < SM_BT + SM_AT + SM_TT) stt[tid - SM_BT - SM_AT] = tor_type[tid - SM_BT - SM_AT];
    else if (tid < SM_BT + SM_AT + SM_TT + SM_MU)
        smu[tid - SM_BT - SM_AT - SM_TT] = (float)multiplicity[tid - SM_BT - SM_AT - SM_TT];
    __syncthreads();

    float eb = 0.0f, ea = 0.0f, et = 0.0f;

    // ---------------- bonds ----------------
    for (int e = tid; e < NB; e += NTHREADS) {
        const float* fr = f + (size_t)(3 * e) * ROW + 6;
        int i0 = (int)fr[0];
        int i1 = (int)fr[ROW];
        int t  = (int)fr[2 * ROW];
        float dx = sc[3 * i0 + 0] - sc[3 * i1 + 0];
        float dy = sc[3 * i0 + 1] - sc[3 * i1 + 1];
        float dz = sc[3 * i0 + 2] - sc[3 * i1 + 2];
        float r  = sqrtf(dx * dx + dy * dy + dz * dz + EPS);
        float k  = sbt[2 * t + 0];
        float r0 = sbt[2 * t + 1];
        float dr = r - r0;
        eb += k * dr * dr;
    }

    // ---------------- angles ----------------
    for (int e = tid; e < NA; e += NTHREADS) {
        const float* fr = f + (size_t)(4 * e) * ROW + 7;
        int a0 = (int)fr[0];
        int a1 = (int)fr[ROW];
        int a2 = (int)fr[2 * ROW];
        int t  = (int)fr[3 * ROW];
        float v1x = sc[3 * a0 + 0] - sc[3 * a1 + 0];
        float v1y = sc[3 * a0 + 1] - sc[3 * a1 + 1];
        float v1z = sc[3 * a0 + 2] - sc[3 * a1 + 2];
        float v2x = sc[3 * a2 + 0] - sc[3 * a1 + 0];
        float v2y = sc[3 * a2 + 1] - sc[3 * a1 + 1];
        float v2z = sc[3 * a2 + 2] - sc[3 * a1 + 2];
        float d11 = v1x * v1x + v1y * v1y + v1z * v1z + EPS;
        float d22 = v2x * v2x + v2y * v2y + v2z * v2z + EPS;
        float d12 = v1x * v2x + v1y * v2y + v1z * v2z;
        float cosang = d12 / (sqrtf(d11) * sqrtf(d22));
        cosang = fminf(fmaxf(cosang, -1.0f + 1e-6f), 1.0f - 1e-6f);
        float theta = acosf(cosang);
        float k  = sat[2 * t + 0];
        float t0 = sat[2 * t + 1];
        float dt = theta - t0;
        ea += k * dt * dt;
    }

    // ---------------- torsions ----------------
    for (int e = tid; e < NT; e += NTHREADS) {
        const float* fr = f + (size_t)(5 * e) * ROW + 8;
        int ti = (int)fr[0];
        int tj = (int)fr[ROW];
        int tk = (int)fr[2 * ROW];
        int tl = (int)fr[3 * ROW];
        int tt = (int)fr[4 * ROW];

        float cix = sc[3 * ti + 0], ciy = sc[3 * ti + 1], ciz = sc[3 * ti + 2];
        float cjx = sc[3 * tj + 0], cjy = sc[3 * tj + 1], cjz = sc[3 * tj + 2];
        float ckx = sc[3 * tk + 0], cky = sc[3 * tk + 1], ckz = sc[3 * tk + 2];
        float clx = sc[3 * tl + 0], cly = sc[3 * tl + 1], clz = sc[3 * tl + 2];

        float b1x = cjx - cix, b1y = cjy - ciy, b1z = cjz - ciz;
        float b2x = ckx - cjx, b2y = cky - cjy, b2z = ckz - cjz;
        float b3x = clx - ckx, b3y = cly - cky, b3z = clz - ckz;

        // n1 = b1 x b2
        float n1x = b1y * b2z - b1z * b2y;
        float n1y = b1z * b2x - b1x * b2z;
        float n1z = b1x * b2y - b1y * b2x;
        // n2 = b2 x b3
        float n2x = b2y * b3z - b2z * b3y;
        float n2y = b2z * b3x - b2x * b3z;
        float n2z = b2x * b3y - b2y * b3x;

        float b2len = sqrtf(b2x * b2x + b2y * b2y + b2z * b2z + EPS);
        float inv = 1.0f / b2len;
        float bnx = b2x * inv, bny = b2y * inv, bnz = b2z * inv;

        // m1 = n1 x b2n
        float m1x = n1y * bnz - n1z * bny;
        float m1y = n1z * bnx - n1x * bnz;
        float m1z = n1x * bny - n1y * bnx;

        float y = m1x * n2x + m1y * n2y + m1z * n2z;
        float x = n1x * n2x + n1y * n2y + n1z * n2z;
        float phi = atan2f(y, x);

        float k  = stt[2 * tt + 0];
        float p0 = stt[2 * tt + 1];
        float nm = smu[tt];
        et += k * (1.0f + cosf(nm * phi - p0));
    }

    // ---------------- block reduction ----------------
    const unsigned FULL = 0xFFFFFFFFu;
    #pragma unroll
    for (int off = 16; off > 0; off >>= 1) {
        eb += __shfl_down_sync(FULL, eb, off);
        ea += __shfl_down_sync(FULL, ea, off);
        et += __shfl_down_sync(FULL, et, off);
    }
    int warp = tid >> 5;
    int lane = tid & 31;
    if (lane == 0) {
        sred[warp]      = eb;
        sred[32 + warp] = ea;
        sred[64 + warp] = et;
    }
    __syncthreads();
    if (warp == 0) {
        float vb = sred[lane];
        float va = sred[32 + lane];
        float vt = sred[64 + lane];
        #pragma unroll
        for (int off = 16; off > 0; off >>= 1) {
            vb += __shfl_down_sync(FULL, vb, off);
            va += __shfl_down_sync(FULL, va, off);
            vt += __shfl_down_sync(FULL, vt, off);
        }
        if (lane == 0) {
            out[3 * b + 0] = opt_pars[0] * vb;
            out[3 * b + 1] = opt_pars[1] * va;
            out[3 * b + 2] = opt_pars[2] * vt;
        }
    }
}

extern "C" void kernel_launch(void* const* d_in, const int* in_sizes, int n_in,
                              void* d_out, int out_size)
{
    const float* feats      = (const float*)d_in[0];
    /* d_in[1] = lengths (unused by reference) */
    const float* bond_type  = (const float*)d_in[2];
    const float* angle_type = (const float*)d_in[3];
    const float* tor_type   = (const float*)d_in[4];
    const int*   mult       = (const int*)  d_in[5];
    const float* opt_pars   = (const float*)d_in[6];
    float*       out        = (float*)d_out;

    cudaFuncSetAttribute(local_energy_kernel,
                         cudaFuncAttributeMaxDynamicSharedMemorySize, SMEM_BYTES);

    local_energy_kernel<<<NBATCH, NTHREADS, SMEM_BYTES>>>(
        feats, bond_type, angle_type, tor_type, mult, opt_pars, out);
}